// round 6
// baseline (speedup 1.0000x reference)
#include <cuda_runtime.h>
#include <cuda_fp16.h>
#include <cuda_bf16.h>
#include <cstdint>

#define NN 100000
#define NE 1600000

// ---------------- device scratch (no allocs allowed) ----------------
__device__ __half g_eh[(size_t)NE * 64];    // edge features fp16, CSR order (205MB)
__device__ __half g_zh0[(size_t)NN * 64];   // z double buffers (fp16)
__device__ __half g_zh1[(size_t)NN * 64];
__device__ float  g_hA[NN * 64];
__device__ float  g_hB[NN * 64];
__device__ float  g_zf[NN * 64];            // final LN output fp32
__device__ int    g_srcn[NE];               // CSR position -> src node
__device__ int    g_pos[NE];                // edge id -> CSR position
__device__ int    g_offs[NN + 1];
__device__ int    g_deg[NN];
__device__ int    g_cur[NN];
__device__ int    g_bsum[128];

// ---------------- CSR build ----------------
__global__ void k_hist(const int* __restrict__ ei) {
    int i = blockIdx.x * blockDim.x + threadIdx.x;
    if (i < NE) atomicAdd(&g_deg[ei[NE + i]], 1);
}
__global__ void k_scan1() {
    int t = threadIdx.x;
    int idx = blockIdx.x * 1024 + t;
    int v = (idx < NN) ? g_deg[idx] : 0;
    if (idx < NN) g_deg[idx] = 0;          // ready for next replay
    int x = v;
    int lane = t & 31, w = t >> 5;
    #pragma unroll
    for (int o = 1; o < 32; o <<= 1) {
        int y = __shfl_up_sync(0xffffffffu, x, o);
        if (lane >= o) x += y;
    }
    __shared__ int ws[32];
    if (lane == 31) ws[w] = x;
    __syncthreads();
    if (w == 0) {
        int y = ws[lane];
        #pragma unroll
        for (int o = 1; o < 32; o <<= 1) {
            int z2 = __shfl_up_sync(0xffffffffu, y, o);
            if (lane >= o) y += z2;
        }
        ws[lane] = y;
    }
    __syncthreads();
    int incl = x + (w > 0 ? ws[w - 1] : 0);
    if (idx < NN) g_offs[idx] = incl - v;
    if (t == 1023) g_bsum[blockIdx.x] = incl;
}
__global__ __launch_bounds__(256) void k_scan23() {
    __shared__ int bs[128];
    __shared__ int ws[4];
    int t = threadIdx.x;
    const int nb = (NN + 1023) >> 10;
    int v = 0, x = 0;
    int lane = t & 31, w = t >> 5;
    if (t < 128) {
        v = (t < nb) ? g_bsum[t] : 0;
        x = v;
        #pragma unroll
        for (int o = 1; o < 32; o <<= 1) {
            int y = __shfl_up_sync(0xffffffffu, x, o);
            if (lane >= o) x += y;
        }
        if (lane == 31) ws[w] = x;
    }
    __syncthreads();
    if (t < 128) {
        int add = 0;
        if (w == 1) add = ws[0];
        else if (w == 2) add = ws[0] + ws[1];
        else if (w == 3) add = ws[0] + ws[1] + ws[2];
        bs[t] = x + add - v;
    }
    __syncthreads();
    int idx = blockIdx.x * 256 + t;
    if (idx < NN) { g_offs[idx] += bs[idx >> 10]; g_cur[idx] = 0; }
    if (idx == 0) g_offs[NN] = NE;
}
__global__ void k_scatter(const int* __restrict__ ei) {
    int i = blockIdx.x * blockDim.x + threadIdx.x;
    if (i < NE) {
        int d = ei[NE + i];
        int p = g_offs[d] + atomicAdd(&g_cur[d], 1);
        g_srcn[p] = ei[i];
        g_pos[i] = p;      // coalesced: edge id -> CSR slot
    }
}

// ---------------- tensor-core GEMM v2: out[pos?pos[r]:r] = A[r] @ W + b --------
// 128 threads, warp = 16x16 output tile; block tile = 16 rows x 64 cols.
// W^T hi/lo fragments held in REGISTERS; A register-prefetch pipeline.
// OUT_MODE: 0 = fp32; 1 = fp16 (smem-staged, optional row scatter); 2 = fp32+fp16.
#define LDSM4(R0,R1,R2,R3,ADDR) \
    asm volatile("ldmatrix.sync.aligned.m8n8.x4.shared.b16 {%0,%1,%2,%3}, [%4];" \
        : "=r"(R0),"=r"(R1),"=r"(R2),"=r"(R3) : "r"(ADDR))
#define MMA_BF16(C0,C1,C2,C3,A0,A1,A2,A3,B0,B1) \
    asm volatile("mma.sync.aligned.m16n8k16.row.col.f32.bf16.bf16.f32 " \
        "{%0,%1,%2,%3},{%4,%5,%6,%7},{%8,%9},{%0,%1,%2,%3};" \
        : "+f"(C0),"+f"(C1),"+f"(C2),"+f"(C3) \
        : "r"(A0),"r"(A1),"r"(A2),"r"(A3),"r"(B0),"r"(B1))

__device__ __forceinline__ uint32_t sm_addr(const void* p) {
    return (uint32_t)__cvta_generic_to_shared(p);
}
__device__ __forceinline__ uint32_t bf2u(float a, float b) {
    __nv_bfloat162 v = __float22bfloat162_rn(make_float2(a, b));
    return *(uint32_t*)&v;
}

template<int OUT_MODE, int TILES>
__global__ __launch_bounds__(128) void k_gemm_tc(
    const float* __restrict__ A,
    const float* __restrict__ W, const float* __restrict__ bias,
    float* __restrict__ outF, __half* __restrict__ outH,
    const int* __restrict__ pos)
{
    __shared__ __align__(16) char smraw[18432];
    __nv_bfloat16 (*Wh)[72] = (__nv_bfloat16(*)[72])smraw;
    __nv_bfloat16 (*Wl)[72] = (__nv_bfloat16(*)[72])(smraw + 9216);
    __nv_bfloat16 (*Ah)[72] = (__nv_bfloat16(*)[72])smraw;
    __nv_bfloat16 (*Al)[72] = (__nv_bfloat16(*)[72])(smraw + 2304);
    __half        (*OS)[72] = (__half(*)[72])      (smraw + 4608);

    int t = threadIdx.x;
    int w = t >> 5, lane = t & 31;
    int tr = lane & 7, sel = lane >> 3;

    for (int i = t; i < 4096; i += 128) {
        int k = i >> 6, n = i & 63;
        float wv = W[i];
        __nv_bfloat16 h = __float2bfloat16(wv);
        Wh[n][k] = h;
        Wl[n][k] = __float2bfloat16(wv - __bfloat162float(h));
    }
    __syncthreads();

    int c0 = w * 16;
    uint32_t bh[4][4], bl[4][4];
    {
        int bn = c0 + tr + ((sel & 2) << 2);
        #pragma unroll
        for (int k = 0; k < 4; k++) {
            int bk = 16 * k + ((sel & 1) << 3);
            LDSM4(bh[k][0], bh[k][1], bh[k][2], bh[k][3], sm_addr(&Wh[bn][bk]));
            LDSM4(bl[k][0], bl[k][1], bl[k][2], bl[k][3], sm_addr(&Wl[bn][bk]));
        }
    }
    __syncthreads();

    float bi[2][2];
    #pragma unroll
    for (int s = 0; s < 2; s++) {
        int cs = c0 + s * 8 + (lane & 3) * 2;
        bi[s][0] = __ldg(&bias[cs]);
        bi[s][1] = __ldg(&bias[cs + 1]);
    }

    int r = t >> 3, q = t & 7;
    int ar = tr + ((sel & 1) << 3);

    long ti0 = (long)blockIdx.x * TILES;
    float4 pfa = __ldcs((const float4*)(A + (ti0 * 16 + r) * 64 + q * 8));
    float4 pfb = __ldcs((const float4*)(A + (ti0 * 16 + r) * 64 + q * 8 + 4));

    for (int it = 0; it < TILES; it++) {
        long ti = ti0 + it;
        {
            float4 a = pfa, b = pfb;
            uint4 hv, lv;
            hv.x = bf2u(a.x, a.y); hv.y = bf2u(a.z, a.w);
            hv.z = bf2u(b.x, b.y); hv.w = bf2u(b.z, b.w);
            float r0 = a.x - __bfloat162float(__float2bfloat16(a.x));
            float r1 = a.y - __bfloat162float(__float2bfloat16(a.y));
            float r2 = a.z - __bfloat162float(__float2bfloat16(a.z));
            float r3 = a.w - __bfloat162float(__float2bfloat16(a.w));
            float r4 = b.x - __bfloat162float(__float2bfloat16(b.x));
            float r5 = b.y - __bfloat162float(__float2bfloat16(b.y));
            float r6 = b.z - __bfloat162float(__float2bfloat16(b.z));
            float r7 = b.w - __bfloat162float(__float2bfloat16(b.w));
            lv.x = bf2u(r0, r1); lv.y = bf2u(r2, r3);
            lv.z = bf2u(r4, r5); lv.w = bf2u(r6, r7);
            *(uint4*)&Ah[r][q * 8] = hv;
            *(uint4*)&Al[r][q * 8] = lv;
        }
        __syncthreads();

        if (it + 1 < TILES) {
            pfa = __ldcs((const float4*)(A + ((ti + 1) * 16 + r) * 64 + q * 8));
            pfb = __ldcs((const float4*)(A + ((ti + 1) * 16 + r) * 64 + q * 8 + 4));
        }

        float acc[2][4];
        #pragma unroll
        for (int s = 0; s < 2; s++) {
            acc[s][0] = bi[s][0]; acc[s][1] = bi[s][1];
            acc[s][2] = bi[s][0]; acc[s][3] = bi[s][1];
        }

        #pragma unroll
        for (int k = 0; k < 4; k++) {
            int ak = 16 * k + ((sel >> 1) << 3);
            uint32_t a0, a1, a2, a3, l0, l1, l2, l3;
            LDSM4(a0, a1, a2, a3, sm_addr(&Ah[ar][ak]));
            LDSM4(l0, l1, l2, l3, sm_addr(&Al[ar][ak]));
            MMA_BF16(acc[0][0],acc[0][1],acc[0][2],acc[0][3], a0,a1,a2,a3, bh[k][0],bh[k][1]);
            MMA_BF16(acc[0][0],acc[0][1],acc[0][2],acc[0][3], a0,a1,a2,a3, bl[k][0],bl[k][1]);
            MMA_BF16(acc[0][0],acc[0][1],acc[0][2],acc[0][3], l0,l1,l2,l3, bh[k][0],bh[k][1]);
            MMA_BF16(acc[1][0],acc[1][1],acc[1][2],acc[1][3], a0,a1,a2,a3, bh[k][2],bh[k][3]);
            MMA_BF16(acc[1][0],acc[1][1],acc[1][2],acc[1][3], a0,a1,a2,a3, bl[k][2],bl[k][3]);
            MMA_BF16(acc[1][0],acc[1][1],acc[1][2],acc[1][3], l0,l1,l2,l3, bh[k][2],bh[k][3]);
        }
        __syncthreads();

        if (OUT_MODE == 1) {
            int r0 = lane >> 2, r1 = r0 + 8;
            #pragma unroll
            for (int s = 0; s < 2; s++) {
                int cs = c0 + s * 8 + (lane & 3) * 2;
                *(__half2*)&OS[r0][cs] = __floats2half2_rn(acc[s][0], acc[s][1]);
                *(__half2*)&OS[r1][cs] = __floats2half2_rn(acc[s][2], acc[s][3]);
            }
            __syncthreads();
            long row = ti * 16 + r;
            long orow = pos ? (long)__ldg(&pos[row]) : row;
            uint4 v = *(uint4*)&OS[r][q * 8];
            *(uint4*)(outH + orow * 64 + q * 8) = v;
        } else {
            long rg0 = ti * 16 + (lane >> 2);
            long rg1 = rg0 + 8;
            #pragma unroll
            for (int s = 0; s < 2; s++) {
                int cs = c0 + s * 8 + (lane & 3) * 2;
                *(float2*)(outF + rg0 * 64 + cs) = make_float2(acc[s][0], acc[s][1]);
                *(float2*)(outF + rg1 * 64 + cs) = make_float2(acc[s][2], acc[s][3]);
                if (OUT_MODE == 2) {
                    *(__half2*)(outH + rg0 * 64 + cs) = __floats2half2_rn(acc[s][0], acc[s][1]);
                    *(__half2*)(outH + rg1 * 64 + cs) = __floats2half2_rn(acc[s][2], acc[s][3]);
                }
            }
        }
    }
}

// ---------------- fused GENConv + LayerNorm/ReLU epilogue ----------------
// e now in CSR order: sequential streaming reads, address independent of indices.
#define AGG_GRID 1563
template<bool RES, bool FINAL>
__global__ __launch_bounds__(256) void k_agg(
    const __half2* __restrict__ z2, const float* __restrict__ hres,
    const float* __restrict__ W, const float* __restrict__ bias,
    const float* __restrict__ tptr,
    const float* __restrict__ gamma, const float* __restrict__ beta,
    float* __restrict__ houtF, __half2* __restrict__ zoutH, float* __restrict__ zfout)
{
    __shared__ float Wsm[4096];
    int t = threadIdx.x;
    for (int i = t; i < 4096; i += 256) Wsm[i] = W[i];
    __syncthreads();

    int w = t >> 5, l = t & 31;
    float tv = __ldg(tptr);
    float bi0 = __ldg(&bias[2 * l]);
    float bi1 = __ldg(&bias[2 * l + 1]);
    float2 ga = ((const float2*)gamma)[l];
    float2 be = ((const float2*)beta)[l];
    const __half2* e2 = (const __half2*)g_eh;
    const float2* W2 = (const float2*)Wsm;

    #pragma unroll 1
    for (int round = 0; round < 8; round++) {
        int node = round * (AGG_GRID * 8) + blockIdx.x * 8 + w;
        if (node >= NN) continue;

        int beg = g_offs[node], end = g_offs[node + 1];
        float d0 = 0.f, d1 = 0.f, s0 = 0.f, s1 = 0.f;
        int p = beg;
        for (; p + 4 <= end; p += 4) {
            // e loads: sequential, index-independent -> issue all up front
            __half2 ea = __ldcs(&e2[(size_t)p * 32 + l]);
            __half2 eb = __ldcs(&e2[(size_t)(p + 1) * 32 + l]);
            __half2 ec = __ldcs(&e2[(size_t)(p + 2) * 32 + l]);
            __half2 ed = __ldcs(&e2[(size_t)(p + 3) * 32 + l]);
            int i0 = __ldg(&g_srcn[p]);
            int i1 = __ldg(&g_srcn[p + 1]);
            int i2 = __ldg(&g_srcn[p + 2]);
            int i3 = __ldg(&g_srcn[p + 3]);
            __half2 za = __ldg(&z2[(size_t)i0 * 32 + l]);
            __half2 zb = __ldg(&z2[(size_t)i1 * 32 + l]);
            __half2 zc = __ldg(&z2[(size_t)i2 * 32 + l]);
            __half2 zd = __ldg(&z2[(size_t)i3 * 32 + l]);
            float2 e0f = __half22float2(ea), z0f = __half22float2(za);
            float2 e1f = __half22float2(eb), z1f = __half22float2(zb);
            float2 e2f = __half22float2(ec), z2f = __half22float2(zc);
            float2 e3f = __half22float2(ed), z3f = __half22float2(zd);
            float m;
            m = fmaxf(e0f.x + z0f.x, 0.f) + 1e-7f; { float x = __expf(m * tv); d0 += x; s0 = fmaf(x, m, s0); }
            m = fmaxf(e0f.y + z0f.y, 0.f) + 1e-7f; { float x = __expf(m * tv); d1 += x; s1 = fmaf(x, m, s1); }
            m = fmaxf(e1f.x + z1f.x, 0.f) + 1e-7f; { float x = __expf(m * tv); d0 += x; s0 = fmaf(x, m, s0); }
            m = fmaxf(e1f.y + z1f.y, 0.f) + 1e-7f; { float x = __expf(m * tv); d1 += x; s1 = fmaf(x, m, s1); }
            m = fmaxf(e2f.x + z2f.x, 0.f) + 1e-7f; { float x = __expf(m * tv); d0 += x; s0 = fmaf(x, m, s0); }
            m = fmaxf(e2f.y + z2f.y, 0.f) + 1e-7f; { float x = __expf(m * tv); d1 += x; s1 = fmaf(x, m, s1); }
            m = fmaxf(e3f.x + z3f.x, 0.f) + 1e-7f; { float x = __expf(m * tv); d0 += x; s0 = fmaf(x, m, s0); }
            m = fmaxf(e3f.y + z3f.y, 0.f) + 1e-7f; { float x = __expf(m * tv); d1 += x; s1 = fmaf(x, m, s1); }
        }
        for (; p < end; p++) {
            float2 ef = __half22float2(__ldcs(&e2[(size_t)p * 32 + l]));
            int si = __ldg(&g_srcn[p]);
            float2 zf2 = __half22float2(__ldg(&z2[(size_t)si * 32 + l]));
            float m0 = fmaxf(ef.x + zf2.x, 0.f) + 1e-7f;
            float m1 = fmaxf(ef.y + zf2.y, 0.f) + 1e-7f;
            float x0 = __expf(m0 * tv);
            float x1 = __expf(m1 * tv);
            d0 += x0; d1 += x1;
            s0 = fmaf(x0, m0, s0); s1 = fmaf(x1, m1, s1);
        }

        float2 zn = __half22float2(z2[(size_t)node * 32 + l]);
        float u0 = __fdividef(s0, d0 + 1e-16f) + zn.x;
        float u1 = __fdividef(s1, d1 + 1e-16f) + zn.y;

        float acc0 = bi0, acc1 = bi1;
        #pragma unroll
        for (int k = 0; k < 64; k += 2) {
            float uk0 = __shfl_sync(0xffffffffu, u0, k >> 1);
            float uk1 = __shfl_sync(0xffffffffu, u1, k >> 1);
            float2 w0 = W2[k * 32 + l];
            float2 w1 = W2[(k + 1) * 32 + l];
            acc0 = fmaf(uk0, w0.x, acc0);
            acc1 = fmaf(uk0, w0.y, acc1);
            acc0 = fmaf(uk1, w1.x, acc0);
            acc1 = fmaf(uk1, w1.y, acc1);
        }
        if (RES) {
            float2 hv = ((const float2*)hres)[(size_t)node * 32 + l];
            acc0 += hv.x; acc1 += hv.y;
        }
        if (!FINAL)
            ((float2*)houtF)[(size_t)node * 32 + l] = make_float2(acc0, acc1);

        float sm = acc0 + acc1;
        #pragma unroll
        for (int o = 16; o > 0; o >>= 1) sm += __shfl_xor_sync(0xffffffffu, sm, o);
        float mu = sm * (1.0f / 64.0f);
        float dx = acc0 - mu, dy = acc1 - mu;
        float qv = dx * dx + dy * dy;
        #pragma unroll
        for (int o = 16; o > 0; o >>= 1) qv += __shfl_xor_sync(0xffffffffu, qv, o);
        float rs = rsqrtf(qv * (1.0f / 64.0f) + 1e-5f);
        float ox = fmaxf(fmaf(dx * rs, ga.x, be.x), 0.f);
        float oy = fmaxf(fmaf(dy * rs, ga.y, be.y), 0.f);
        if (FINAL)
            ((float2*)zfout)[(size_t)node * 32 + l] = make_float2(ox, oy);
        else
            zoutH[(size_t)node * 32 + l] = __floats2half2_rn(ox, oy);
    }
}

// ---------------- launch ----------------
extern "C" void kernel_launch(void* const* d_in, const int* in_sizes, int n_in,
                              void* d_out, int out_size)
{
    const float* x         = (const float*)d_in[0];
    const float* edge_attr = (const float*)d_in[1];
    const int*   ei        = (const int*)d_in[2];
    const float* W_ne      = (const float*)d_in[3];
    const float* b_ne      = (const float*)d_in[4];
    const float* W_ee      = (const float*)d_in[5];
    const float* b_ee      = (const float*)d_in[6];
    const float* W_conv    = (const float*)d_in[7];
    const float* b_conv    = (const float*)d_in[8];
    const float* tarr      = (const float*)d_in[9];
    const float* gamma     = (const float*)d_in[10];
    const float* beta      = (const float*)d_in[11];
    const float* W_lin     = (const float*)d_in[12];
    const float* b_lin     = (const float*)d_in[13];
    float* out = (float*)d_out;

    float *p_hA, *p_hB, *p_zf;
    __half *p_eh, *p_zh0, *p_zh1;
    int *p_pos;
    cudaGetSymbolAddress((void**)&p_eh,  g_eh);
    cudaGetSymbolAddress((void**)&p_zh0, g_zh0);
    cudaGetSymbolAddress((void**)&p_zh1, g_zh1);
    cudaGetSymbolAddress((void**)&p_hA,  g_hA);
    cudaGetSymbolAddress((void**)&p_hB,  g_hB);
    cudaGetSymbolAddress((void**)&p_zf,  g_zf);
    cudaGetSymbolAddress((void**)&p_pos, g_pos);

    const int NB_E  = (NE + 255) / 256;
    const int NB_S  = (NN + 1023) / 1024;
    const int NB_SC = (NN + 255) / 256;

    // CSR prefix + scatter (must precede edge GEMM: it scatters via g_pos)
    k_hist  <<<NB_E, 256>>>(ei);
    k_scan1 <<<NB_S, 1024>>>();
    k_scan23<<<NB_SC, 256>>>();
    k_scatter<<<NB_E, 256>>>(ei);
    // edge encoder: sequential reads, fp16 rows scattered to CSR slots (write-side perm)
    k_gemm_tc<1, 16><<<6250, 128>>>(edge_attr, W_ee, b_ee, nullptr, p_eh, p_pos);
    // node encoder
    k_gemm_tc<2, 10><<<625, 128>>>(x, W_ne, b_ne, p_hA, p_zh0, nullptr);

    // fused conv (+LN/ReLU producing next layer's z)
    k_agg<false, false><<<AGG_GRID, 256>>>((const __half2*)p_zh0, nullptr,
        W_conv,         b_conv,       tarr,     gamma + 64,  beta + 64,  p_hB, (__half2*)p_zh1, nullptr);
    k_agg<true,  false><<<AGG_GRID, 256>>>((const __half2*)p_zh1, p_hB,
        W_conv + 4096,  b_conv + 64,  tarr + 1, gamma + 128, beta + 128, p_hA, (__half2*)p_zh0, nullptr);
    k_agg<true,  false><<<AGG_GRID, 256>>>((const __half2*)p_zh0, p_hA,
        W_conv + 8192,  b_conv + 128, tarr + 2, gamma + 192, beta + 192, p_hB, (__half2*)p_zh1, nullptr);
    k_agg<true,  true ><<<AGG_GRID, 256>>>((const __half2*)p_zh1, p_hB,
        W_conv + 12288, b_conv + 192, tarr + 3, gamma,       beta,       nullptr, nullptr, p_zf);

    // final linear
    k_gemm_tc<0, 10><<<625, 128>>>(p_zf, W_lin, b_lin, out, nullptr, nullptr);
}

// round 7
// speedup vs baseline: 1.1072x; 1.1072x over previous
#include <cuda_runtime.h>
#include <cuda_fp16.h>
#include <cuda_bf16.h>
#include <cstdint>

#define NN 100000
#define NE 1600000

// ---------------- device scratch (no allocs allowed) ----------------
__device__ __half g_eh[(size_t)NE * 64];    // edge features fp16, CSR order (205MB)
__device__ __half g_zh0[(size_t)NN * 64];   // z double buffers (fp16)
__device__ __half g_zh1[(size_t)NN * 64];
__device__ __half g_u[(size_t)NN * 64];     // aggregated u = aggr + z (fp16)
__device__ float  g_hA[NN * 64];
__device__ float  g_hB[NN * 64];
__device__ float  g_zf[NN * 64];            // final LN output fp32
__device__ int    g_srcn[NE];               // CSR position -> src node
__device__ int    g_pos[NE];                // edge id -> CSR position
__device__ int    g_offs[NN + 1];
__device__ int    g_deg[NN];
__device__ int    g_cur[NN];
__device__ int    g_bsum[128];

// ---------------- CSR build ----------------
__global__ void k_hist(const int* __restrict__ ei) {
    int i = blockIdx.x * blockDim.x + threadIdx.x;
    if (i < NE) atomicAdd(&g_deg[ei[NE + i]], 1);
}
__global__ void k_scan1() {
    int t = threadIdx.x;
    int idx = blockIdx.x * 1024 + t;
    int v = (idx < NN) ? g_deg[idx] : 0;
    if (idx < NN) g_deg[idx] = 0;
    int x = v;
    int lane = t & 31, w = t >> 5;
    #pragma unroll
    for (int o = 1; o < 32; o <<= 1) {
        int y = __shfl_up_sync(0xffffffffu, x, o);
        if (lane >= o) x += y;
    }
    __shared__ int ws[32];
    if (lane == 31) ws[w] = x;
    __syncthreads();
    if (w == 0) {
        int y = ws[lane];
        #pragma unroll
        for (int o = 1; o < 32; o <<= 1) {
            int z2 = __shfl_up_sync(0xffffffffu, y, o);
            if (lane >= o) y += z2;
        }
        ws[lane] = y;
    }
    __syncthreads();
    int incl = x + (w > 0 ? ws[w - 1] : 0);
    if (idx < NN) g_offs[idx] = incl - v;
    if (t == 1023) g_bsum[blockIdx.x] = incl;
}
__global__ __launch_bounds__(256) void k_scan23() {
    __shared__ int bs[128];
    __shared__ int ws[4];
    int t = threadIdx.x;
    const int nb = (NN + 1023) >> 10;
    int v = 0, x = 0;
    int lane = t & 31, w = t >> 5;
    if (t < 128) {
        v = (t < nb) ? g_bsum[t] : 0;
        x = v;
        #pragma unroll
        for (int o = 1; o < 32; o <<= 1) {
            int y = __shfl_up_sync(0xffffffffu, x, o);
            if (lane >= o) x += y;
        }
        if (lane == 31) ws[w] = x;
    }
    __syncthreads();
    if (t < 128) {
        int add = 0;
        if (w == 1) add = ws[0];
        else if (w == 2) add = ws[0] + ws[1];
        else if (w == 3) add = ws[0] + ws[1] + ws[2];
        bs[t] = x + add - v;
    }
    __syncthreads();
    int idx = blockIdx.x * 256 + t;
    if (idx < NN) { g_offs[idx] += bs[idx >> 10]; g_cur[idx] = 0; }
    if (idx == 0) g_offs[NN] = NE;
}
__global__ void k_scatter(const int* __restrict__ ei) {
    int i = blockIdx.x * blockDim.x + threadIdx.x;
    if (i < NE) {
        int d = ei[NE + i];
        int p = g_offs[d] + atomicAdd(&g_cur[d], 1);
        g_srcn[p] = ei[i];
        g_pos[i] = p;
    }
}

// ---------------- shared GEMM plumbing ----------------
#define LDSM4(R0,R1,R2,R3,ADDR) \
    asm volatile("ldmatrix.sync.aligned.m8n8.x4.shared.b16 {%0,%1,%2,%3}, [%4];" \
        : "=r"(R0),"=r"(R1),"=r"(R2),"=r"(R3) : "r"(ADDR))
#define MMA_BF16(C0,C1,C2,C3,A0,A1,A2,A3,B0,B1) \
    asm volatile("mma.sync.aligned.m16n8k16.row.col.f32.bf16.bf16.f32 " \
        "{%0,%1,%2,%3},{%4,%5,%6,%7},{%8,%9},{%0,%1,%2,%3};" \
        : "+f"(C0),"+f"(C1),"+f"(C2),"+f"(C3) \
        : "r"(A0),"r"(A1),"r"(A2),"r"(A3),"r"(B0),"r"(B1))

__device__ __forceinline__ uint32_t sm_addr(const void* p) {
    return (uint32_t)__cvta_generic_to_shared(p);
}
__device__ __forceinline__ uint32_t bf2u(float a, float b) {
    __nv_bfloat162 v = __float22bfloat162_rn(make_float2(a, b));
    return *(uint32_t*)&v;
}

// ---------------- encoder/final GEMM: out[pos?pos[r]:r] = A[r] @ W + b --------
// OUT_MODE: 0 = fp32; 1 = fp16 (smem-staged, optional row scatter); 2 = fp32+fp16.
template<int OUT_MODE, int TILES>
__global__ __launch_bounds__(128) void k_gemm_tc(
    const float* __restrict__ A,
    const float* __restrict__ W, const float* __restrict__ bias,
    float* __restrict__ outF, __half* __restrict__ outH,
    const int* __restrict__ pos)
{
    __shared__ __align__(16) char smraw[18432];
    __nv_bfloat16 (*Wh)[72] = (__nv_bfloat16(*)[72])smraw;
    __nv_bfloat16 (*Wl)[72] = (__nv_bfloat16(*)[72])(smraw + 9216);
    __nv_bfloat16 (*Ah)[72] = (__nv_bfloat16(*)[72])smraw;
    __nv_bfloat16 (*Al)[72] = (__nv_bfloat16(*)[72])(smraw + 2304);
    __half        (*OS)[72] = (__half(*)[72])      (smraw + 4608);

    int t = threadIdx.x;
    int w = t >> 5, lane = t & 31;
    int tr = lane & 7, sel = lane >> 3;

    for (int i = t; i < 4096; i += 128) {
        int k = i >> 6, n = i & 63;
        float wv = W[i];
        __nv_bfloat16 h = __float2bfloat16(wv);
        Wh[n][k] = h;
        Wl[n][k] = __float2bfloat16(wv - __bfloat162float(h));
    }
    __syncthreads();

    int c0 = w * 16;
    uint32_t bh[4][4], bl[4][4];
    {
        int bn = c0 + tr + ((sel & 2) << 2);
        #pragma unroll
        for (int k = 0; k < 4; k++) {
            int bk = 16 * k + ((sel & 1) << 3);
            LDSM4(bh[k][0], bh[k][1], bh[k][2], bh[k][3], sm_addr(&Wh[bn][bk]));
            LDSM4(bl[k][0], bl[k][1], bl[k][2], bl[k][3], sm_addr(&Wl[bn][bk]));
        }
    }
    __syncthreads();

    float bi[2][2];
    #pragma unroll
    for (int s = 0; s < 2; s++) {
        int cs = c0 + s * 8 + (lane & 3) * 2;
        bi[s][0] = __ldg(&bias[cs]);
        bi[s][1] = __ldg(&bias[cs + 1]);
    }

    int r = t >> 3, q = t & 7;
    int ar = tr + ((sel & 1) << 3);

    long ti0 = (long)blockIdx.x * TILES;
    float4 pfa = __ldcs((const float4*)(A + (ti0 * 16 + r) * 64 + q * 8));
    float4 pfb = __ldcs((const float4*)(A + (ti0 * 16 + r) * 64 + q * 8 + 4));

    for (int it = 0; it < TILES; it++) {
        long ti = ti0 + it;
        {
            float4 a = pfa, b = pfb;
            uint4 hv, lv;
            hv.x = bf2u(a.x, a.y); hv.y = bf2u(a.z, a.w);
            hv.z = bf2u(b.x, b.y); hv.w = bf2u(b.z, b.w);
            float r0 = a.x - __bfloat162float(__float2bfloat16(a.x));
            float r1 = a.y - __bfloat162float(__float2bfloat16(a.y));
            float r2 = a.z - __bfloat162float(__float2bfloat16(a.z));
            float r3 = a.w - __bfloat162float(__float2bfloat16(a.w));
            float r4 = b.x - __bfloat162float(__float2bfloat16(b.x));
            float r5 = b.y - __bfloat162float(__float2bfloat16(b.y));
            float r6 = b.z - __bfloat162float(__float2bfloat16(b.z));
            float r7 = b.w - __bfloat162float(__float2bfloat16(b.w));
            lv.x = bf2u(r0, r1); lv.y = bf2u(r2, r3);
            lv.z = bf2u(r4, r5); lv.w = bf2u(r6, r7);
            *(uint4*)&Ah[r][q * 8] = hv;
            *(uint4*)&Al[r][q * 8] = lv;
        }
        __syncthreads();

        if (it + 1 < TILES) {
            pfa = __ldcs((const float4*)(A + ((ti + 1) * 16 + r) * 64 + q * 8));
            pfb = __ldcs((const float4*)(A + ((ti + 1) * 16 + r) * 64 + q * 8 + 4));
        }

        float acc[2][4];
        #pragma unroll
        for (int s = 0; s < 2; s++) {
            acc[s][0] = bi[s][0]; acc[s][1] = bi[s][1];
            acc[s][2] = bi[s][0]; acc[s][3] = bi[s][1];
        }

        #pragma unroll
        for (int k = 0; k < 4; k++) {
            int ak = 16 * k + ((sel >> 1) << 3);
            uint32_t a0, a1, a2, a3, l0, l1, l2, l3;
            LDSM4(a0, a1, a2, a3, sm_addr(&Ah[ar][ak]));
            LDSM4(l0, l1, l2, l3, sm_addr(&Al[ar][ak]));
            MMA_BF16(acc[0][0],acc[0][1],acc[0][2],acc[0][3], a0,a1,a2,a3, bh[k][0],bh[k][1]);
            MMA_BF16(acc[0][0],acc[0][1],acc[0][2],acc[0][3], a0,a1,a2,a3, bl[k][0],bl[k][1]);
            MMA_BF16(acc[0][0],acc[0][1],acc[0][2],acc[0][3], l0,l1,l2,l3, bh[k][0],bh[k][1]);
            MMA_BF16(acc[1][0],acc[1][1],acc[1][2],acc[1][3], a0,a1,a2,a3, bh[k][2],bh[k][3]);
            MMA_BF16(acc[1][0],acc[1][1],acc[1][2],acc[1][3], a0,a1,a2,a3, bl[k][2],bl[k][3]);
            MMA_BF16(acc[1][0],acc[1][1],acc[1][2],acc[1][3], l0,l1,l2,l3, bh[k][2],bh[k][3]);
        }
        __syncthreads();

        if (OUT_MODE == 1) {
            int r0 = lane >> 2, r1 = r0 + 8;
            #pragma unroll
            for (int s = 0; s < 2; s++) {
                int cs = c0 + s * 8 + (lane & 3) * 2;
                *(__half2*)&OS[r0][cs] = __floats2half2_rn(acc[s][0], acc[s][1]);
                *(__half2*)&OS[r1][cs] = __floats2half2_rn(acc[s][2], acc[s][3]);
            }
            __syncthreads();
            long row = ti * 16 + r;
            long orow = pos ? (long)__ldg(&pos[row]) : row;
            uint4 v = *(uint4*)&OS[r][q * 8];
            *(uint4*)(outH + orow * 64 + q * 8) = v;
        } else {
            long rg0 = ti * 16 + (lane >> 2);
            long rg1 = rg0 + 8;
            #pragma unroll
            for (int s = 0; s < 2; s++) {
                int cs = c0 + s * 8 + (lane & 3) * 2;
                *(float2*)(outF + rg0 * 64 + cs) = make_float2(acc[s][0], acc[s][1]);
                *(float2*)(outF + rg1 * 64 + cs) = make_float2(acc[s][2], acc[s][3]);
                if (OUT_MODE == 2) {
                    *(__half2*)(outH + rg0 * 64 + cs) = __floats2half2_rn(acc[s][0], acc[s][1]);
                    *(__half2*)(outH + rg1 * 64 + cs) = __floats2half2_rn(acc[s][2], acc[s][3]);
                }
            }
        }
    }
}

// ---------------- conv GEMM with fused residual + LN + ReLU epilogue ----------
// h' = u @ W + b (+ hres);  z_next = relu(LN(h', gamma, beta))
// FINAL: only z (fp32) written; else h' fp32 + z fp16.
template<bool RES, bool FINAL, int TILES>
__global__ __launch_bounds__(128) void k_gemm_conv(
    const __half* __restrict__ U,
    const float* __restrict__ W, const float* __restrict__ bias,
    const float* __restrict__ hres,
    const float* __restrict__ gamma, const float* __restrict__ beta,
    float* __restrict__ houtF, __half* __restrict__ zoutH, float* __restrict__ zfout)
{
    __shared__ __align__(16) char smraw[18432];
    __nv_bfloat16 (*Wh)[72]  = (__nv_bfloat16(*)[72])smraw;
    __nv_bfloat16 (*Wl)[72]  = (__nv_bfloat16(*)[72])(smraw + 9216);
    __nv_bfloat16 (*Ah)[72]  = (__nv_bfloat16(*)[72])smraw;
    __nv_bfloat16 (*Al)[72]  = (__nv_bfloat16(*)[72])(smraw + 2304);
    float         (*OSf)[72] = (float(*)[72])       (smraw + 4608);   // 16x72 f32

    int t = threadIdx.x;
    int w = t >> 5, lane = t & 31;
    int tr = lane & 7, sel = lane >> 3;

    for (int i = t; i < 4096; i += 128) {
        int k = i >> 6, n = i & 63;
        float wv = W[i];
        __nv_bfloat16 h = __float2bfloat16(wv);
        Wh[n][k] = h;
        Wl[n][k] = __float2bfloat16(wv - __bfloat162float(h));
    }
    __syncthreads();

    int c0 = w * 16;
    uint32_t bh[4][4], bl[4][4];
    {
        int bn = c0 + tr + ((sel & 2) << 2);
        #pragma unroll
        for (int k = 0; k < 4; k++) {
            int bk = 16 * k + ((sel & 1) << 3);
            LDSM4(bh[k][0], bh[k][1], bh[k][2], bh[k][3], sm_addr(&Wh[bn][bk]));
            LDSM4(bl[k][0], bl[k][1], bl[k][2], bl[k][3], sm_addr(&Wl[bn][bk]));
        }
    }
    __syncthreads();

    float bi[2][2];
    #pragma unroll
    for (int s = 0; s < 2; s++) {
        int cs = c0 + s * 8 + (lane & 3) * 2;
        bi[s][0] = __ldg(&bias[cs]);
        bi[s][1] = __ldg(&bias[cs + 1]);
    }

    int r = t >> 3, q = t & 7;
    int ar = tr + ((sel & 1) << 3);

    // per-thread LN params for columns q*8 .. q*8+7
    float4 ga0 = __ldg((const float4*)(gamma + q * 8));
    float4 ga1 = __ldg((const float4*)(gamma + q * 8 + 4));
    float4 be0 = __ldg((const float4*)(beta  + q * 8));
    float4 be1 = __ldg((const float4*)(beta  + q * 8 + 4));

    long ti0 = (long)blockIdx.x * TILES;
    uint4 pfu = __ldcs((const uint4*)(U + (ti0 * 16 + r) * 64 + q * 8));   // 8 halves

    for (int it = 0; it < TILES; it++) {
        long ti = ti0 + it;
        {
            const __half2* hp = (const __half2*)&pfu;
            uint4 hv, lv;
            float f[8];
            #pragma unroll
            for (int j = 0; j < 4; j++) {
                float2 fv = __half22float2(hp[j]);
                f[2 * j] = fv.x; f[2 * j + 1] = fv.y;
            }
            hv.x = bf2u(f[0], f[1]); hv.y = bf2u(f[2], f[3]);
            hv.z = bf2u(f[4], f[5]); hv.w = bf2u(f[6], f[7]);
            float l[8];
            #pragma unroll
            for (int j = 0; j < 8; j++)
                l[j] = f[j] - __bfloat162float(__float2bfloat16(f[j]));
            lv.x = bf2u(l[0], l[1]); lv.y = bf2u(l[2], l[3]);
            lv.z = bf2u(l[4], l[5]); lv.w = bf2u(l[6], l[7]);
            *(uint4*)&Ah[r][q * 8] = hv;
            *(uint4*)&Al[r][q * 8] = lv;
        }
        __syncthreads();

        if (it + 1 < TILES)
            pfu = __ldcs((const uint4*)(U + ((ti + 1) * 16 + r) * 64 + q * 8));

        float acc[2][4];
        #pragma unroll
        for (int s = 0; s < 2; s++) {
            acc[s][0] = bi[s][0]; acc[s][1] = bi[s][1];
            acc[s][2] = bi[s][0]; acc[s][3] = bi[s][1];
        }

        #pragma unroll
        for (int k = 0; k < 4; k++) {
            int ak = 16 * k + ((sel >> 1) << 3);
            uint32_t a0, a1, a2, a3, l0, l1, l2, l3;
            LDSM4(a0, a1, a2, a3, sm_addr(&Ah[ar][ak]));
            LDSM4(l0, l1, l2, l3, sm_addr(&Al[ar][ak]));
            MMA_BF16(acc[0][0],acc[0][1],acc[0][2],acc[0][3], a0,a1,a2,a3, bh[k][0],bh[k][1]);
            MMA_BF16(acc[0][0],acc[0][1],acc[0][2],acc[0][3], a0,a1,a2,a3, bl[k][0],bl[k][1]);
            MMA_BF16(acc[0][0],acc[0][1],acc[0][2],acc[0][3], l0,l1,l2,l3, bh[k][0],bh[k][1]);
            MMA_BF16(acc[1][0],acc[1][1],acc[1][2],acc[1][3], a0,a1,a2,a3, bh[k][2],bh[k][3]);
            MMA_BF16(acc[1][0],acc[1][1],acc[1][2],acc[1][3], a0,a1,a2,a3, bl[k][2],bl[k][3]);
            MMA_BF16(acc[1][0],acc[1][1],acc[1][2],acc[1][3], l0,l1,l2,l3, bh[k][2],bh[k][3]);
        }
        __syncthreads();

        // stage fp32 results
        {
            int r0 = lane >> 2, r1 = r0 + 8;
            #pragma unroll
            for (int s = 0; s < 2; s++) {
                int cs = c0 + s * 8 + (lane & 3) * 2;
                *(float2*)&OSf[r0][cs] = make_float2(acc[s][0], acc[s][1]);
                *(float2*)&OSf[r1][cs] = make_float2(acc[s][2], acc[s][3]);
            }
        }
        __syncthreads();

        // epilogue: residual + LN + relu; 8 threads per row
        {
            long row = ti * 16 + r;
            float4 va = *(float4*)&OSf[r][q * 8];
            float4 vb = *(float4*)&OSf[r][q * 8 + 4];
            if (RES) {
                float4 ha = __ldcs((const float4*)(hres + row * 64 + q * 8));
                float4 hb = __ldcs((const float4*)(hres + row * 64 + q * 8 + 4));
                va.x += ha.x; va.y += ha.y; va.z += ha.z; va.w += ha.w;
                vb.x += hb.x; vb.y += hb.y; vb.z += hb.z; vb.w += hb.w;
            }
            float s = va.x + va.y + va.z + va.w + vb.x + vb.y + vb.z + vb.w;
            float ss = va.x*va.x + va.y*va.y + va.z*va.z + va.w*va.w
                     + vb.x*vb.x + vb.y*vb.y + vb.z*vb.z + vb.w*vb.w;
            #pragma unroll
            for (int m = 1; m < 8; m <<= 1) {
                s  += __shfl_xor_sync(0xffffffffu, s,  m);
                ss += __shfl_xor_sync(0xffffffffu, ss, m);
            }
            float mu = s * (1.0f / 64.0f);
            float var = fmaxf(ss * (1.0f / 64.0f) - mu * mu, 0.0f);
            float rs = rsqrtf(var + 1e-5f);
            float z0 = fmaxf(fmaf((va.x - mu) * rs, ga0.x, be0.x), 0.f);
            float z1 = fmaxf(fmaf((va.y - mu) * rs, ga0.y, be0.y), 0.f);
            float z2 = fmaxf(fmaf((va.z - mu) * rs, ga0.z, be0.z), 0.f);
            float z3 = fmaxf(fmaf((va.w - mu) * rs, ga0.w, be0.w), 0.f);
            float z4 = fmaxf(fmaf((vb.x - mu) * rs, ga1.x, be1.x), 0.f);
            float z5 = fmaxf(fmaf((vb.y - mu) * rs, ga1.y, be1.y), 0.f);
            float z6 = fmaxf(fmaf((vb.z - mu) * rs, ga1.z, be1.z), 0.f);
            float z7 = fmaxf(fmaf((vb.w - mu) * rs, ga1.w, be1.w), 0.f);
            if (FINAL) {
                *(float4*)(zfout + row * 64 + q * 8)     = make_float4(z0, z1, z2, z3);
                *(float4*)(zfout + row * 64 + q * 8 + 4) = make_float4(z4, z5, z6, z7);
            } else {
                *(float4*)(houtF + row * 64 + q * 8)     = va;
                *(float4*)(houtF + row * 64 + q * 8 + 4) = vb;
                uint4 zv;
                __half2 p0 = __floats2half2_rn(z0, z1);
                __half2 p1 = __floats2half2_rn(z2, z3);
                __half2 p2 = __floats2half2_rn(z4, z5);
                __half2 p3 = __floats2half2_rn(z6, z7);
                zv.x = *(uint32_t*)&p0; zv.y = *(uint32_t*)&p1;
                zv.z = *(uint32_t*)&p2; zv.w = *(uint32_t*)&p3;
                *(uint4*)(zoutH + row * 64 + q * 8) = zv;
            }
        }
    }
}

// ---------------- aggregation only: u = softmax-aggr + z  (fp16 out) ----------
#define AGG_GRID 1563
__global__ __launch_bounds__(256) void k_agg_lite(
    const __half2* __restrict__ z2, const float* __restrict__ tptr,
    __half2* __restrict__ uout)
{
    int t = threadIdx.x;
    int w = t >> 5, l = t & 31;
    float tv = __ldg(tptr);
    const __half2* e2 = (const __half2*)g_eh;

    #pragma unroll 1
    for (int round = 0; round < 8; round++) {
        int node = round * (AGG_GRID * 8) + blockIdx.x * 8 + w;
        if (node >= NN) continue;

        int beg = g_offs[node], end = g_offs[node + 1];
        float d0 = 0.f, d1 = 0.f, s0 = 0.f, s1 = 0.f;
        int p = beg;
        for (; p + 4 <= end; p += 4) {
            __half2 ea = __ldcs(&e2[(size_t)p * 32 + l]);
            __half2 eb = __ldcs(&e2[(size_t)(p + 1) * 32 + l]);
            __half2 ec = __ldcs(&e2[(size_t)(p + 2) * 32 + l]);
            __half2 ed = __ldcs(&e2[(size_t)(p + 3) * 32 + l]);
            int i0 = __ldg(&g_srcn[p]);
            int i1 = __ldg(&g_srcn[p + 1]);
            int i2 = __ldg(&g_srcn[p + 2]);
            int i3 = __ldg(&g_srcn[p + 3]);
            __half2 za = __ldg(&z2[(size_t)i0 * 32 + l]);
            __half2 zb = __ldg(&z2[(size_t)i1 * 32 + l]);
            __half2 zc = __ldg(&z2[(size_t)i2 * 32 + l]);
            __half2 zd = __ldg(&z2[(size_t)i3 * 32 + l]);
            float2 e0f = __half22float2(ea), z0f = __half22float2(za);
            float2 e1f = __half22float2(eb), z1f = __half22float2(zb);
            float2 e2f = __half22float2(ec), z2f = __half22float2(zc);
            float2 e3f = __half22float2(ed), z3f = __half22float2(zd);
            float m;
            m = fmaxf(e0f.x + z0f.x, 0.f) + 1e-7f; { float x = __expf(m * tv); d0 += x; s0 = fmaf(x, m, s0); }
            m = fmaxf(e0f.y + z0f.y, 0.f) + 1e-7f; { float x = __expf(m * tv); d1 += x; s1 = fmaf(x, m, s1); }
            m = fmaxf(e1f.x + z1f.x, 0.f) + 1e-7f; { float x = __expf(m * tv); d0 += x; s0 = fmaf(x, m, s0); }
            m = fmaxf(e1f.y + z1f.y, 0.f) + 1e-7f; { float x = __expf(m * tv); d1 += x; s1 = fmaf(x, m, s1); }
            m = fmaxf(e2f.x + z2f.x, 0.f) + 1e-7f; { float x = __expf(m * tv); d0 += x; s0 = fmaf(x, m, s0); }
            m = fmaxf(e2f.y + z2f.y, 0.f) + 1e-7f; { float x = __expf(m * tv); d1 += x; s1 = fmaf(x, m, s1); }
            m = fmaxf(e3f.x + z3f.x, 0.f) + 1e-7f; { float x = __expf(m * tv); d0 += x; s0 = fmaf(x, m, s0); }
            m = fmaxf(e3f.y + z3f.y, 0.f) + 1e-7f; { float x = __expf(m * tv); d1 += x; s1 = fmaf(x, m, s1); }
        }
        for (; p < end; p++) {
            float2 ef = __half22float2(__ldcs(&e2[(size_t)p * 32 + l]));
            int si = __ldg(&g_srcn[p]);
            float2 zf2 = __half22float2(__ldg(&z2[(size_t)si * 32 + l]));
            float m0 = fmaxf(ef.x + zf2.x, 0.f) + 1e-7f;
            float m1 = fmaxf(ef.y + zf2.y, 0.f) + 1e-7f;
            float x0 = __expf(m0 * tv);
            float x1 = __expf(m1 * tv);
            d0 += x0; d1 += x1;
            s0 = fmaf(x0, m0, s0); s1 = fmaf(x1, m1, s1);
        }

        float2 zn = __half22float2(z2[(size_t)node * 32 + l]);
        float u0 = __fdividef(s0, d0 + 1e-16f) + zn.x;
        float u1 = __fdividef(s1, d1 + 1e-16f) + zn.y;
        uout[(size_t)node * 32 + l] = __floats2half2_rn(u0, u1);
    }
}

// ---------------- launch ----------------
extern "C" void kernel_launch(void* const* d_in, const int* in_sizes, int n_in,
                              void* d_out, int out_size)
{
    const float* x         = (const float*)d_in[0];
    const float* edge_attr = (const float*)d_in[1];
    const int*   ei        = (const int*)d_in[2];
    const float* W_ne      = (const float*)d_in[3];
    const float* b_ne      = (const float*)d_in[4];
    const float* W_ee      = (const float*)d_in[5];
    const float* b_ee      = (const float*)d_in[6];
    const float* W_conv    = (const float*)d_in[7];
    const float* b_conv    = (const float*)d_in[8];
    const float* tarr      = (const float*)d_in[9];
    const float* gamma     = (const float*)d_in[10];
    const float* beta      = (const float*)d_in[11];
    const float* W_lin     = (const float*)d_in[12];
    const float* b_lin     = (const float*)d_in[13];
    float* out = (float*)d_out;

    float *p_hA, *p_hB, *p_zf;
    __half *p_eh, *p_zh0, *p_zh1, *p_u;
    int *p_pos;
    cudaGetSymbolAddress((void**)&p_eh,  g_eh);
    cudaGetSymbolAddress((void**)&p_zh0, g_zh0);
    cudaGetSymbolAddress((void**)&p_zh1, g_zh1);
    cudaGetSymbolAddress((void**)&p_u,   g_u);
    cudaGetSymbolAddress((void**)&p_hA,  g_hA);
    cudaGetSymbolAddress((void**)&p_hB,  g_hB);
    cudaGetSymbolAddress((void**)&p_zf,  g_zf);
    cudaGetSymbolAddress((void**)&p_pos, g_pos);

    const int NB_E  = (NE + 255) / 256;
    const int NB_S  = (NN + 1023) / 1024;
    const int NB_SC = (NN + 255) / 256;

    // CSR
    k_hist  <<<NB_E, 256>>>(ei);
    k_scan1 <<<NB_S, 1024>>>();
    k_scan23<<<NB_SC, 256>>>();
    k_scatter<<<NB_E, 256>>>(ei);
    // encoders
    k_gemm_tc<1, 16><<<6250, 128>>>(edge_attr, W_ee, b_ee, nullptr, p_eh, p_pos);
    k_gemm_tc<2, 10><<<625, 128>>>(x, W_ne, b_ne, p_hA, p_zh0, nullptr);

    // layer 0: u from z=h0; h1 = u@W0+b0 (no residual); z1 = relu(LN(h1, g1, b1))
    k_agg_lite<<<AGG_GRID, 256>>>((const __half2*)p_zh0, tarr, (__half2*)p_u);
    k_gemm_conv<false, false, 10><<<625, 128>>>(p_u, W_conv, b_conv, nullptr,
        gamma + 64, beta + 64, p_hB, p_zh1, nullptr);
    // layer 1
    k_agg_lite<<<AGG_GRID, 256>>>((const __half2*)p_zh1, tarr + 1, (__half2*)p_u);
    k_gemm_conv<true, false, 10><<<625, 128>>>(p_u, W_conv + 4096, b_conv + 64, p_hB,
        gamma + 128, beta + 128, p_hA, p_zh0, nullptr);
    // layer 2
    k_agg_lite<<<AGG_GRID, 256>>>((const __half2*)p_zh0, tarr + 2, (__half2*)p_u);
    k_gemm_conv<true, false, 10><<<625, 128>>>(p_u, W_conv + 8192, b_conv + 128, p_hA,
        gamma + 192, beta + 192, p_hB, p_zh1, nullptr);
    // layer 3 (final LN uses gamma0/beta0; writes z fp32 only)
    k_agg_lite<<<AGG_GRID, 256>>>((const __half2*)p_zh1, tarr + 3, (__half2*)p_u);
    k_gemm_conv<true, true, 10><<<625, 128>>>(p_u, W_conv + 12288, b_conv + 192, p_hB,
        gamma, beta, nullptr, nullptr, p_zf);

    // final linear
    k_gemm_tc<0, 10><<<625, 128>>>(p_zf, W_lin, b_lin, out, nullptr, nullptr);
}

// round 8
// speedup vs baseline: 1.2978x; 1.1721x over previous
#include <cuda_runtime.h>
#include <cuda_fp16.h>
#include <cuda_bf16.h>
#include <cstdint>

#define NN 100000
#define NE 1600000

// ---------------- device scratch ----------------
__device__ __half g_eh[(size_t)NE * 64];    // edge features fp16, CSR order
__device__ __half g_zh0[(size_t)NN * 64];
__device__ __half g_zh1[(size_t)NN * 64];
__device__ __half g_u[(size_t)NN * 64];
__device__ float  g_hA[NN * 64];
__device__ float  g_hB[NN * 64];
__device__ float  g_zf[NN * 64];
__device__ int    g_srcn[NE];
__device__ int    g_pos[NE];
__device__ int    g_rank[NE];
__device__ int    g_offs[NN + 1];
__device__ int    g_deg[NN];
__device__ int    g_bsum[128];

// ---------------- CSR build ----------------
__global__ void k_hist(const int* __restrict__ ei) {
    int i = blockIdx.x * blockDim.x + threadIdx.x;
    if (i < NE) g_rank[i] = atomicAdd(&g_deg[ei[NE + i]], 1);
}
__global__ void k_scan1() {
    int t = threadIdx.x;
    int idx = blockIdx.x * 1024 + t;
    int v = (idx < NN) ? g_deg[idx] : 0;
    if (idx < NN) g_deg[idx] = 0;
    int x = v;
    int lane = t & 31, w = t >> 5;
    #pragma unroll
    for (int o = 1; o < 32; o <<= 1) {
        int y = __shfl_up_sync(0xffffffffu, x, o);
        if (lane >= o) x += y;
    }
    __shared__ int ws[32];
    if (lane == 31) ws[w] = x;
    __syncthreads();
    if (w == 0) {
        int y = ws[lane];
        #pragma unroll
        for (int o = 1; o < 32; o <<= 1) {
            int z2 = __shfl_up_sync(0xffffffffu, y, o);
            if (lane >= o) y += z2;
        }
        ws[lane] = y;
    }
    __syncthreads();
    int incl = x + (w > 0 ? ws[w - 1] : 0);
    if (idx < NN) g_offs[idx] = incl - v;
    if (t == 1023) g_bsum[blockIdx.x] = incl;
}
__global__ __launch_bounds__(256) void k_scan23() {
    __shared__ int bs[128];
    __shared__ int ws[4];
    int t = threadIdx.x;
    const int nb = (NN + 1023) >> 10;
    int v = 0, x = 0;
    int lane = t & 31, w = t >> 5;
    if (t < 128) {
        v = (t < nb) ? g_bsum[t] : 0;
        x = v;
        #pragma unroll
        for (int o = 1; o < 32; o <<= 1) {
            int y = __shfl_up_sync(0xffffffffu, x, o);
            if (lane >= o) x += y;
        }
        if (lane == 31) ws[w] = x;
    }
    __syncthreads();
    if (t < 128) {
        int add = 0;
        if (w == 1) add = ws[0];
        else if (w == 2) add = ws[0] + ws[1];
        else if (w == 3) add = ws[0] + ws[1] + ws[2];
        bs[t] = x + add - v;
    }
    __syncthreads();
    int idx = blockIdx.x * 256 + t;
    if (idx < NN) g_offs[idx] += bs[idx >> 10];
    if (idx == 0) g_offs[NN] = NE;
}
__global__ void k_scatter(const int* __restrict__ ei) {
    int i = blockIdx.x * blockDim.x + threadIdx.x;
    if (i < NE) {
        int d = ei[NE + i];
        int p = g_offs[d] + g_rank[i];    // no atomic
        g_srcn[p] = ei[i];
        g_pos[i] = p;
    }
}

// ---------------- GEMM plumbing ----------------
#define LDSM4(R0,R1,R2,R3,ADDR) \
    asm volatile("ldmatrix.sync.aligned.m8n8.x4.shared.b16 {%0,%1,%2,%3}, [%4];" \
        : "=r"(R0),"=r"(R1),"=r"(R2),"=r"(R3) : "r"(ADDR))
#define MMA_BF16(C0,C1,C2,C3,A0,A1,A2,A3,B0,B1) \
    asm volatile("mma.sync.aligned.m16n8k16.row.col.f32.bf16.bf16.f32 " \
        "{%0,%1,%2,%3},{%4,%5,%6,%7},{%8,%9},{%0,%1,%2,%3};" \
        : "+f"(C0),"+f"(C1),"+f"(C2),"+f"(C3) \
        : "r"(A0),"r"(A1),"r"(A2),"r"(A3),"r"(B0),"r"(B1))
#define MMA_F16(C0,C1,C2,C3,A0,A1,A2,A3,B0,B1) \
    asm volatile("mma.sync.aligned.m16n8k16.row.col.f32.f16.f16.f32 " \
        "{%0,%1,%2,%3},{%4,%5,%6,%7},{%8,%9},{%0,%1,%2,%3};" \
        : "+f"(C0),"+f"(C1),"+f"(C2),"+f"(C3) \
        : "r"(A0),"r"(A1),"r"(A2),"r"(A3),"r"(B0),"r"(B1))

__device__ __forceinline__ uint32_t sm_addr(const void* p) {
    return (uint32_t)__cvta_generic_to_shared(p);
}
__device__ __forceinline__ uint32_t bf2u(float a, float b) {
    __nv_bfloat162 v = __float22bfloat162_rn(make_float2(a, b));
    return *(uint32_t*)&v;
}
__device__ __forceinline__ uint32_t hf2u(float a, float b) {
    __half2 v = __floats2half2_rn(a, b);
    return *(uint32_t*)&v;
}
__device__ __forceinline__ float ex2f(float x) {
    float r; asm("ex2.approx.f32 %0, %1;" : "=f"(r) : "f"(x)); return r;
}

// ---------------- bf16 3-pass GEMM (node encoder / final linear) -------------
// OUT_MODE: 0 = fp32; 2 = fp32 + fp16 copy.
template<int OUT_MODE, int TILES>
__global__ __launch_bounds__(128) void k_gemm_tc(
    const float* __restrict__ A,
    const float* __restrict__ W, const float* __restrict__ bias,
    float* __restrict__ outF, __half* __restrict__ outH)
{
    __shared__ __align__(16) char smraw[18432];
    __nv_bfloat16 (*Wh)[72] = (__nv_bfloat16(*)[72])smraw;
    __nv_bfloat16 (*Wl)[72] = (__nv_bfloat16(*)[72])(smraw + 9216);
    __nv_bfloat16 (*Ah)[72] = (__nv_bfloat16(*)[72])smraw;
    __nv_bfloat16 (*Al)[72] = (__nv_bfloat16(*)[72])(smraw + 2304);

    int t = threadIdx.x;
    int w = t >> 5, lane = t & 31;
    int tr = lane & 7, sel = lane >> 3;

    for (int i = t; i < 4096; i += 128) {
        int k = i >> 6, n = i & 63;
        float wv = W[i];
        __nv_bfloat16 h = __float2bfloat16(wv);
        Wh[n][k] = h;
        Wl[n][k] = __float2bfloat16(wv - __bfloat162float(h));
    }
    __syncthreads();

    int c0 = w * 16;
    uint32_t bh[4][4], bl[4][4];
    {
        int bn = c0 + tr + ((sel & 2) << 2);
        #pragma unroll
        for (int k = 0; k < 4; k++) {
            int bk = 16 * k + ((sel & 1) << 3);
            LDSM4(bh[k][0], bh[k][1], bh[k][2], bh[k][3], sm_addr(&Wh[bn][bk]));
            LDSM4(bl[k][0], bl[k][1], bl[k][2], bl[k][3], sm_addr(&Wl[bn][bk]));
        }
    }
    __syncthreads();

    float bi[2][2];
    #pragma unroll
    for (int s = 0; s < 2; s++) {
        int cs = c0 + s * 8 + (lane & 3) * 2;
        bi[s][0] = __ldg(&bias[cs]);
        bi[s][1] = __ldg(&bias[cs + 1]);
    }

    int r = t >> 3, q = t & 7;
    int ar = tr + ((sel & 1) << 3);

    long ti0 = (long)blockIdx.x * TILES;
    float4 pfa = __ldcs((const float4*)(A + (ti0 * 16 + r) * 64 + q * 8));
    float4 pfb = __ldcs((const float4*)(A + (ti0 * 16 + r) * 64 + q * 8 + 4));

    for (int it = 0; it < TILES; it++) {
        long ti = ti0 + it;
        {
            float4 a = pfa, b = pfb;
            uint4 hv, lv;
            hv.x = bf2u(a.x, a.y); hv.y = bf2u(a.z, a.w);
            hv.z = bf2u(b.x, b.y); hv.w = bf2u(b.z, b.w);
            float r0 = a.x - __bfloat162float(__float2bfloat16(a.x));
            float r1 = a.y - __bfloat162float(__float2bfloat16(a.y));
            float r2 = a.z - __bfloat162float(__float2bfloat16(a.z));
            float r3 = a.w - __bfloat162float(__float2bfloat16(a.w));
            float r4 = b.x - __bfloat162float(__float2bfloat16(b.x));
            float r5 = b.y - __bfloat162float(__float2bfloat16(b.y));
            float r6 = b.z - __bfloat162float(__float2bfloat16(b.z));
            float r7 = b.w - __bfloat162float(__float2bfloat16(b.w));
            lv.x = bf2u(r0, r1); lv.y = bf2u(r2, r3);
            lv.z = bf2u(r4, r5); lv.w = bf2u(r6, r7);
            *(uint4*)&Ah[r][q * 8] = hv;
            *(uint4*)&Al[r][q * 8] = lv;
        }
        __syncthreads();

        if (it + 1 < TILES) {
            pfa = __ldcs((const float4*)(A + ((ti + 1) * 16 + r) * 64 + q * 8));
            pfb = __ldcs((const float4*)(A + ((ti + 1) * 16 + r) * 64 + q * 8 + 4));
        }

        float acc[2][4];
        #pragma unroll
        for (int s = 0; s < 2; s++) {
            acc[s][0] = bi[s][0]; acc[s][1] = bi[s][1];
            acc[s][2] = bi[s][0]; acc[s][3] = bi[s][1];
        }

        #pragma unroll
        for (int k = 0; k < 4; k++) {
            int ak = 16 * k + ((sel >> 1) << 3);
            uint32_t a0, a1, a2, a3, l0, l1, l2, l3;
            LDSM4(a0, a1, a2, a3, sm_addr(&Ah[ar][ak]));
            LDSM4(l0, l1, l2, l3, sm_addr(&Al[ar][ak]));
            MMA_BF16(acc[0][0],acc[0][1],acc[0][2],acc[0][3], a0,a1,a2,a3, bh[k][0],bh[k][1]);
            MMA_BF16(acc[0][0],acc[0][1],acc[0][2],acc[0][3], a0,a1,a2,a3, bl[k][0],bl[k][1]);
            MMA_BF16(acc[0][0],acc[0][1],acc[0][2],acc[0][3], l0,l1,l2,l3, bh[k][0],bh[k][1]);
            MMA_BF16(acc[1][0],acc[1][1],acc[1][2],acc[1][3], a0,a1,a2,a3, bh[k][2],bh[k][3]);
            MMA_BF16(acc[1][0],acc[1][1],acc[1][2],acc[1][3], a0,a1,a2,a3, bl[k][2],bl[k][3]);
            MMA_BF16(acc[1][0],acc[1][1],acc[1][2],acc[1][3], l0,l1,l2,l3, bh[k][2],bh[k][3]);
        }
        __syncthreads();

        long rg0 = ti * 16 + (lane >> 2);
        long rg1 = rg0 + 8;
        #pragma unroll
        for (int s = 0; s < 2; s++) {
            int cs = c0 + s * 8 + (lane & 3) * 2;
            *(float2*)(outF + rg0 * 64 + cs) = make_float2(acc[s][0], acc[s][1]);
            *(float2*)(outF + rg1 * 64 + cs) = make_float2(acc[s][2], acc[s][3]);
            if (OUT_MODE == 2) {
                *(__half2*)(outH + rg0 * 64 + cs) = __floats2half2_rn(acc[s][0], acc[s][1]);
                *(__half2*)(outH + rg1 * 64 + cs) = __floats2half2_rn(acc[s][2], acc[s][3]);
            }
        }
    }
}

// ---------------- edge encoder: fp16 A single-pass, W fp16 hi/lo ----------------
template<int TILES>
__global__ __launch_bounds__(128) void k_gemm_edge(
    const float* __restrict__ A,
    const float* __restrict__ W, const float* __restrict__ bias,
    __half* __restrict__ outH, const int* __restrict__ pos)
{
    __shared__ __align__(16) char smraw[18432];
    __half (*Wh)[72]  = (__half(*)[72])smraw;
    __half (*Wl)[72]  = (__half(*)[72])(smraw + 9216);
    __half (*Ahh)[72] = (__half(*)[72])smraw;
    __half (*OS)[72]  = (__half(*)[72])(smraw + 2304);

    int t = threadIdx.x;
    int w = t >> 5, lane = t & 31;
    int tr = lane & 7, sel = lane >> 3;

    for (int i = t; i < 4096; i += 128) {
        int k = i >> 6, n = i & 63;
        float wv = W[i];
        __half h = __float2half_rn(wv);
        Wh[n][k] = h;
        Wl[n][k] = __float2half_rn(wv - __half2float(h));
    }
    __syncthreads();

    int c0 = w * 16;
    uint32_t bh[4][4], bl[4][4];
    {
        int bn = c0 + tr + ((sel & 2) << 2);
        #pragma unroll
        for (int k = 0; k < 4; k++) {
            int bk = 16 * k + ((sel & 1) << 3);
            LDSM4(bh[k][0], bh[k][1], bh[k][2], bh[k][3], sm_addr(&Wh[bn][bk]));
            LDSM4(bl[k][0], bl[k][1], bl[k][2], bl[k][3], sm_addr(&Wl[bn][bk]));
        }
    }
    __syncthreads();

    float bi[2][2];
    #pragma unroll
    for (int s = 0; s < 2; s++) {
        int cs = c0 + s * 8 + (lane & 3) * 2;
        bi[s][0] = __ldg(&bias[cs]);
        bi[s][1] = __ldg(&bias[cs + 1]);
    }

    int r = t >> 3, q = t & 7;
    int ar = tr + ((sel & 1) << 3);

    long ti0 = (long)blockIdx.x * TILES;
    float4 pfa = __ldcs((const float4*)(A + (ti0 * 16 + r) * 64 + q * 8));
    float4 pfb = __ldcs((const float4*)(A + (ti0 * 16 + r) * 64 + q * 8 + 4));

    for (int it = 0; it < TILES; it++) {
        long ti = ti0 + it;
        {
            uint4 hv;
            hv.x = hf2u(pfa.x, pfa.y); hv.y = hf2u(pfa.z, pfa.w);
            hv.z = hf2u(pfb.x, pfb.y); hv.w = hf2u(pfb.z, pfb.w);
            *(uint4*)&Ahh[r][q * 8] = hv;
        }
        __syncthreads();

        if (it + 1 < TILES) {
            pfa = __ldcs((const float4*)(A + ((ti + 1) * 16 + r) * 64 + q * 8));
            pfb = __ldcs((const float4*)(A + ((ti + 1) * 16 + r) * 64 + q * 8 + 4));
        }

        float acc[2][4];
        #pragma unroll
        for (int s = 0; s < 2; s++) {
            acc[s][0] = bi[s][0]; acc[s][1] = bi[s][1];
            acc[s][2] = bi[s][0]; acc[s][3] = bi[s][1];
        }

        #pragma unroll
        for (int k = 0; k < 4; k++) {
            int ak = 16 * k + ((sel >> 1) << 3);
            uint32_t a0, a1, a2, a3;
            LDSM4(a0, a1, a2, a3, sm_addr(&Ahh[ar][ak]));
            MMA_F16(acc[0][0],acc[0][1],acc[0][2],acc[0][3], a0,a1,a2,a3, bh[k][0],bh[k][1]);
            MMA_F16(acc[0][0],acc[0][1],acc[0][2],acc[0][3], a0,a1,a2,a3, bl[k][0],bl[k][1]);
            MMA_F16(acc[1][0],acc[1][1],acc[1][2],acc[1][3], a0,a1,a2,a3, bh[k][2],bh[k][3]);
            MMA_F16(acc[1][0],acc[1][1],acc[1][2],acc[1][3], a0,a1,a2,a3, bl[k][2],bl[k][3]);
        }
        __syncthreads();

        {
            int r0 = lane >> 2, r1 = r0 + 8;
            #pragma unroll
            for (int s = 0; s < 2; s++) {
                int cs = c0 + s * 8 + (lane & 3) * 2;
                *(__half2*)&OS[r0][cs] = __floats2half2_rn(acc[s][0], acc[s][1]);
                *(__half2*)&OS[r1][cs] = __floats2half2_rn(acc[s][2], acc[s][3]);
            }
            __syncthreads();
            long row = ti * 16 + r;
            long orow = (long)__ldg(&pos[row]);
            uint4 v = *(uint4*)&OS[r][q * 8];
            *(uint4*)(outH + orow * 64 + q * 8) = v;
        }
    }
}

// ---------------- conv GEMM (u fp16 exact, W fp16 hi/lo) + LN epilogue --------
template<bool RES, bool FINAL, int TILES>
__global__ __launch_bounds__(128) void k_gemm_conv(
    const __half* __restrict__ U,
    const float* __restrict__ W, const float* __restrict__ bias,
    const float* __restrict__ hres,
    const float* __restrict__ gamma, const float* __restrict__ beta,
    float* __restrict__ houtF, __half* __restrict__ zoutH, float* __restrict__ zfout)
{
    __shared__ __align__(16) char smraw[18432];
    __half (*Wh)[72]  = (__half(*)[72])smraw;
    __half (*Wl)[72]  = (__half(*)[72])(smraw + 9216);
    __half (*Ahh)[72] = (__half(*)[72])smraw;
    float  (*OSf)[72] = (float(*)[72]) (smraw + 2304);

    int t = threadIdx.x;
    int w = t >> 5, lane = t & 31;
    int tr = lane & 7, sel = lane >> 3;

    for (int i = t; i < 4096; i += 128) {
        int k = i >> 6, n = i & 63;
        float wv = W[i];
        __half h = __float2half_rn(wv);
        Wh[n][k] = h;
        Wl[n][k] = __float2half_rn(wv - __half2float(h));
    }
    __syncthreads();

    int c0 = w * 16;
    uint32_t bh[4][4], bl[4][4];
    {
        int bn = c0 + tr + ((sel & 2) << 2);
        #pragma unroll
        for (int k = 0; k < 4; k++) {
            int bk = 16 * k + ((sel & 1) << 3);
            LDSM4(bh[k][0], bh[k][1], bh[k][2], bh[k][3], sm_addr(&Wh[bn][bk]));
            LDSM4(bl[k][0], bl[k][1], bl[k][2], bl[k][3], sm_addr(&Wl[bn][bk]));
        }
    }
    __syncthreads();

    float bi[2][2];
    #pragma unroll
    for (int s = 0; s < 2; s++) {
        int cs = c0 + s * 8 + (lane & 3) * 2;
        bi[s][0] = __ldg(&bias[cs]);
        bi[s][1] = __ldg(&bias[cs + 1]);
    }

    int r = t >> 3, q = t & 7;
    int ar = tr + ((sel & 1) << 3);

    float4 ga0 = __ldg((const float4*)(gamma + q * 8));
    float4 ga1 = __ldg((const float4*)(gamma + q * 8 + 4));
    float4 be0 = __ldg((const float4*)(beta  + q * 8));
    float4 be1 = __ldg((const float4*)(beta  + q * 8 + 4));

    long ti0 = (long)blockIdx.x * TILES;
    uint4 pfu = __ldcs((const uint4*)(U + (ti0 * 16 + r) * 64 + q * 8));

    for (int it = 0; it < TILES; it++) {
        long ti = ti0 + it;
        *(uint4*)&Ahh[r][q * 8] = pfu;    // u already fp16 — direct copy
        __syncthreads();

        if (it + 1 < TILES)
            pfu = __ldcs((const uint4*)(U + ((ti + 1) * 16 + r) * 64 + q * 8));

        float acc[2][4];
        #pragma unroll
        for (int s = 0; s < 2; s++) {
            acc[s][0] = bi[s][0]; acc[s][1] = bi[s][1];
            acc[s][2] = bi[s][0]; acc[s][3] = bi[s][1];
        }

        #pragma unroll
        for (int k = 0; k < 4; k++) {
            int ak = 16 * k + ((sel >> 1) << 3);
            uint32_t a0, a1, a2, a3;
            LDSM4(a0, a1, a2, a3, sm_addr(&Ahh[ar][ak]));
            MMA_F16(acc[0][0],acc[0][1],acc[0][2],acc[0][3], a0,a1,a2,a3, bh[k][0],bh[k][1]);
            MMA_F16(acc[0][0],acc[0][1],acc[0][2],acc[0][3], a0,a1,a2,a3, bl[k][0],bl[k][1]);
            MMA_F16(acc[1][0],acc[1][1],acc[1][2],acc[1][3], a0,a1,a2,a3, bh[k][2],bh[k][3]);
            MMA_F16(acc[1][0],acc[1][1],acc[1][2],acc[1][3], a0,a1,a2,a3, bl[k][2],bl[k][3]);
        }
        __syncthreads();

        {
            int r0 = lane >> 2, r1 = r0 + 8;
            #pragma unroll
            for (int s = 0; s < 2; s++) {
                int cs = c0 + s * 8 + (lane & 3) * 2;
                *(float2*)&OSf[r0][cs] = make_float2(acc[s][0], acc[s][1]);
                *(float2*)&OSf[r1][cs] = make_float2(acc[s][2], acc[s][3]);
            }
        }
        __syncthreads();

        {
            long row = ti * 16 + r;
            float4 va = *(float4*)&OSf[r][q * 8];
            float4 vb = *(float4*)&OSf[r][q * 8 + 4];
            if (RES) {
                float4 ha = __ldcs((const float4*)(hres + row * 64 + q * 8));
                float4 hb = __ldcs((const float4*)(hres + row * 64 + q * 8 + 4));
                va.x += ha.x; va.y += ha.y; va.z += ha.z; va.w += ha.w;
                vb.x += hb.x; vb.y += hb.y; vb.z += hb.z; vb.w += hb.w;
            }
            float s = va.x + va.y + va.z + va.w + vb.x + vb.y + vb.z + vb.w;
            float ss = va.x*va.x + va.y*va.y + va.z*va.z + va.w*va.w
                     + vb.x*vb.x + vb.y*vb.y + vb.z*vb.z + vb.w*vb.w;
            #pragma unroll
            for (int m = 1; m < 8; m <<= 1) {
                s  += __shfl_xor_sync(0xffffffffu, s,  m);
                ss += __shfl_xor_sync(0xffffffffu, ss, m);
            }
            float mu = s * (1.0f / 64.0f);
            float var = fmaxf(ss * (1.0f / 64.0f) - mu * mu, 0.0f);
            float rs = rsqrtf(var + 1e-5f);
            float z0 = fmaxf(fmaf((va.x - mu) * rs, ga0.x, be0.x), 0.f);
            float z1 = fmaxf(fmaf((va.y - mu) * rs, ga0.y, be0.y), 0.f);
            float z2 = fmaxf(fmaf((va.z - mu) * rs, ga0.z, be0.z), 0.f);
            float z3 = fmaxf(fmaf((va.w - mu) * rs, ga0.w, be0.w), 0.f);
            float z4 = fmaxf(fmaf((vb.x - mu) * rs, ga1.x, be1.x), 0.f);
            float z5 = fmaxf(fmaf((vb.y - mu) * rs, ga1.y, be1.y), 0.f);
            float z6 = fmaxf(fmaf((vb.z - mu) * rs, ga1.z, be1.z), 0.f);
            float z7 = fmaxf(fmaf((vb.w - mu) * rs, ga1.w, be1.w), 0.f);
            if (FINAL) {
                *(float4*)(zfout + row * 64 + q * 8)     = make_float4(z0, z1, z2, z3);
                *(float4*)(zfout + row * 64 + q * 8 + 4) = make_float4(z4, z5, z6, z7);
            } else {
                *(float4*)(houtF + row * 64 + q * 8)     = va;
                *(float4*)(houtF + row * 64 + q * 8 + 4) = vb;
                uint4 zv;
                zv.x = hf2u(z0, z1); zv.y = hf2u(z2, z3);
                zv.z = hf2u(z4, z5); zv.w = hf2u(z6, z7);
                *(uint4*)(zoutH + row * 64 + q * 8) = zv;
            }
        }
    }
}

// ---------------- aggregation: u = softmax-aggr + z (half2 math) -------------
#define AGG_GRID 1563
__global__ __launch_bounds__(256) void k_agg_lite(
    const __half2* __restrict__ z2, const float* __restrict__ tptr,
    __half2* __restrict__ uout)
{
    int t = threadIdx.x;
    int w = t >> 5, l = t & 31;
    float tv = __ldg(tptr);
    float kf = tv * 1.44269504f;           // t * log2(e)
    const __half2 zero2 = __float2half2_rn(0.f);
    const __half2 eps2  = __float2half2_rn(1e-7f);
    const __half2* e2 = (const __half2*)g_eh;

    #pragma unroll 1
    for (int round = 0; round < 8; round++) {
        int node = round * (AGG_GRID * 8) + blockIdx.x * 8 + w;
        if (node >= NN) continue;

        int beg = g_offs[node], end = g_offs[node + 1];
        float d0 = 0.f, d1 = 0.f, s0 = 0.f, s1 = 0.f;
        int p = beg;
        for (; p + 4 <= end; p += 4) {
            __half2 ea = __ldcs(&e2[(size_t)p * 32 + l]);
            __half2 eb = __ldcs(&e2[(size_t)(p + 1) * 32 + l]);
            __half2 ec = __ldcs(&e2[(size_t)(p + 2) * 32 + l]);
            __half2 ed = __ldcs(&e2[(size_t)(p + 3) * 32 + l]);
            int i0 = __ldg(&g_srcn[p]);
            int i1 = __ldg(&g_srcn[p + 1]);
            int i2 = __ldg(&g_srcn[p + 2]);
            int i3 = __ldg(&g_srcn[p + 3]);
            __half2 za = __ldg(&z2[(size_t)i0 * 32 + l]);
            __half2 zb = __ldg(&z2[(size_t)i1 * 32 + l]);
            __half2 zc = __ldg(&z2[(size_t)i2 * 32 + l]);
            __half2 zd = __ldg(&z2[(size_t)i3 * 32 + l]);
            __half2 ma = __hadd2(__hmax2(__hadd2(ea, za), zero2), eps2);
            __half2 mb = __hadd2(__hmax2(__hadd2(eb, zb), zero2), eps2);
            __half2 mc = __hadd2(__hmax2(__hadd2(ec, zc), zero2), eps2);
            __half2 md = __hadd2(__hmax2(__hadd2(ed, zd), zero2), eps2);
            float m0, m1, x0, x1;
            m0 = __low2float(ma); m1 = __high2float(ma);
            x0 = ex2f(m0 * kf); x1 = ex2f(m1 * kf);
            d0 += x0; s0 = fmaf(x0, m0, s0);
            d1 += x1; s1 = fmaf(x1, m1, s1);
            m0 = __low2float(mb); m1 = __high2float(mb);
            x0 = ex2f(m0 * kf); x1 = ex2f(m1 * kf);
            d0 += x0; s0 = fmaf(x0, m0, s0);
            d1 += x1; s1 = fmaf(x1, m1, s1);
            m0 = __low2float(mc); m1 = __high2float(mc);
            x0 = ex2f(m0 * kf); x1 = ex2f(m1 * kf);
            d0 += x0; s0 = fmaf(x0, m0, s0);
            d1 += x1; s1 = fmaf(x1, m1, s1);
            m0 = __low2float(md); m1 = __high2float(md);
            x0 = ex2f(m0 * kf); x1 = ex2f(m1 * kf);
            d0 += x0; s0 = fmaf(x0, m0, s0);
            d1 += x1; s1 = fmaf(x1, m1, s1);
        }
        for (; p < end; p++) {
            __half2 ef = __ldcs(&e2[(size_t)p * 32 + l]);
            int si = __ldg(&g_srcn[p]);
            __half2 zv = __ldg(&z2[(size_t)si * 32 + l]);
            __half2 ma = __hadd2(__hmax2(__hadd2(ef, zv), zero2), eps2);
            float m0 = __low2float(ma), m1 = __high2float(ma);
            float x0 = ex2f(m0 * kf), x1 = ex2f(m1 * kf);
            d0 += x0; s0 = fmaf(x0, m0, s0);
            d1 += x1; s1 = fmaf(x1, m1, s1);
        }

        float2 zn = __half22float2(z2[(size_t)node * 32 + l]);
        float u0 = __fdividef(s0, d0 + 1e-16f) + zn.x;
        float u1 = __fdividef(s1, d1 + 1e-16f) + zn.y;
        uout[(size_t)node * 32 + l] = __floats2half2_rn(u0, u1);
    }
}

// ---------------- launch ----------------
extern "C" void kernel_launch(void* const* d_in, const int* in_sizes, int n_in,
                              void* d_out, int out_size)
{
    const float* x         = (const float*)d_in[0];
    const float* edge_attr = (const float*)d_in[1];
    const int*   ei        = (const int*)d_in[2];
    const float* W_ne      = (const float*)d_in[3];
    const float* b_ne      = (const float*)d_in[4];
    const float* W_ee      = (const float*)d_in[5];
    const float* b_ee      = (const float*)d_in[6];
    const float* W_conv    = (const float*)d_in[7];
    const float* b_conv    = (const float*)d_in[8];
    const float* tarr      = (const float*)d_in[9];
    const float* gamma     = (const float*)d_in[10];
    const float* beta      = (const float*)d_in[11];
    const float* W_lin     = (const float*)d_in[12];
    const float* b_lin     = (const float*)d_in[13];
    float* out = (float*)d_out;

    float *p_hA, *p_hB, *p_zf;
    __half *p_eh, *p_zh0, *p_zh1, *p_u;
    int *p_pos;
    cudaGetSymbolAddress((void**)&p_eh,  g_eh);
    cudaGetSymbolAddress((void**)&p_zh0, g_zh0);
    cudaGetSymbolAddress((void**)&p_zh1, g_zh1);
    cudaGetSymbolAddress((void**)&p_u,   g_u);
    cudaGetSymbolAddress((void**)&p_hA,  g_hA);
    cudaGetSymbolAddress((void**)&p_hB,  g_hB);
    cudaGetSymbolAddress((void**)&p_zf,  g_zf);
    cudaGetSymbolAddress((void**)&p_pos, g_pos);

    const int NB_E  = (NE + 255) / 256;
    const int NB_S  = (NN + 1023) / 1024;
    const int NB_SC = (NN + 255) / 256;

    // CSR
    k_hist  <<<NB_E, 256>>>(ei);
    k_scan1 <<<NB_S, 1024>>>();
    k_scan23<<<NB_SC, 256>>>();
    k_scatter<<<NB_E, 256>>>(ei);
    // encoders
    k_gemm_edge<16><<<6250, 128>>>(edge_attr, W_ee, b_ee, p_eh, p_pos);
    k_gemm_tc<2, 10><<<625, 128>>>(x, W_ne, b_ne, p_hA, p_zh0);

    // layer 0
    k_agg_lite<<<AGG_GRID, 256>>>((const __half2*)p_zh0, tarr, (__half2*)p_u);
    k_gemm_conv<false, false, 10><<<625, 128>>>(p_u, W_conv, b_conv, nullptr,
        gamma + 64, beta + 64, p_hB, p_zh1, nullptr);
    // layer 1
    k_agg_lite<<<AGG_GRID, 256>>>((const __half2*)p_zh1, tarr + 1, (__half2*)p_u);
    k_gemm_conv<true, false, 10><<<625, 128>>>(p_u, W_conv + 4096, b_conv + 64, p_hB,
        gamma + 128, beta + 128, p_hA, p_zh0, nullptr);
    // layer 2
    k_agg_lite<<<AGG_GRID, 256>>>((const __half2*)p_zh0, tarr + 2, (__half2*)p_u);
    k_gemm_conv<true, false, 10><<<625, 128>>>(p_u, W_conv + 8192, b_conv + 128, p_hA,
        gamma + 192, beta + 192, p_hB, p_zh1, nullptr);
    // layer 3
    k_agg_lite<<<AGG_GRID, 256>>>((const __half2*)p_zh1, tarr + 3, (__half2*)p_u);
    k_gemm_conv<true, true, 10><<<625, 128>>>(p_u, W_conv + 12288, b_conv + 192, p_hB,
        gamma, beta, nullptr, nullptr, p_zf);

    // final linear
    k_gemm_tc<0, 10><<<625, 128>>>(p_zf, W_lin, b_lin, out, nullptr);
}